// round 7
// baseline (speedup 1.0000x reference)
#include <cuda_runtime.h>
#include <cstdint>

#define B_ 256
#define L_ 4096
#define H_ 64
#define V_ 64

__device__ float g_K[V_ * H_];
__device__ float g_invd[V_];
__device__ float g_G[V_ * V_];

// ---------------------------------------------------------------------------
// Phase 1a: vocab table (V==64 collapses embed+FF+LN to a 64x64 LUT)
// ---------------------------------------------------------------------------
__global__ void build_table_kernel(const float* __restrict__ embed_W,
                                   const float* __restrict__ w1,
                                   const float* __restrict__ b1,
                                   const float* __restrict__ w2,
                                   const float* __restrict__ b2,
                                   const float* __restrict__ lnw,
                                   const float* __restrict__ lnb)
{
    __shared__ float e[H_], a[2 * H_], hrow[H_], red[H_];
    const int v = blockIdx.x, t = threadIdx.x;

    e[t] = embed_W[v * H_ + t];
    __syncthreads();

    float a0 = b1[t], a1 = b1[t + H_];
    #pragma unroll 8
    for (int k = 0; k < H_; k++) {
        float ek = e[k];
        a0 += ek * w1[k * 2 * H_ + t];
        a1 += ek * w1[k * 2 * H_ + t + H_];
    }
    a[t] = fmaxf(a0, 0.f); a[t + H_] = fmaxf(a1, 0.f);
    __syncthreads();

    float f = b2[t];
    #pragma unroll 8
    for (int o = 0; o < 2 * H_; o++) f += a[o] * w2[o * H_ + t];
    hrow[t] = e[t] + f;
    __syncthreads();

    float mu = 0.f;
    #pragma unroll 8
    for (int j = 0; j < H_; j++) mu += hrow[j];
    mu *= (1.f / H_);
    float var = 0.f;
    #pragma unroll 8
    for (int j = 0; j < H_; j++) { float d = hrow[j] - mu; var += d * d; }
    var *= (1.f / H_);

    float kv = (hrow[t] - mu) * rsqrtf(var + 1e-5f) * lnw[t] + lnb[t];
    g_K[v * H_ + t] = kv;
    red[t] = kv * kv;
    __syncthreads();
    if (t == 0) {
        float d = 0.f;
        #pragma unroll 8
        for (int j = 0; j < H_; j++) d += red[j];
        g_invd[v] = 1.f / (d + 1e-6f);
    }
}

// Phase 1b: Gram matrix G = K K^T
__global__ void build_gram_kernel()
{
    __shared__ float Kt[V_ * H_];
    const int t = threadIdx.x;
    for (int i = t; i < V_ * H_ / 4; i += H_)
        reinterpret_cast<float4*>(Kt)[i] = reinterpret_cast<const float4*>(g_K)[i];
    __syncthreads();
    const int r = blockIdx.x;
    float acc = 0.f;
    #pragma unroll 8
    for (int i = 0; i < H_; i++) acc += Kt[r * H_ + i] * Kt[t * H_ + i];
    g_G[r * V_ + t] = acc;
}

// ---------------------------------------------------------------------------
// tf32 mma.sync (valid on plain compute_103; no sm_103a feature needed)
// ---------------------------------------------------------------------------
__device__ __forceinline__ void mma_tf32(float d[4],
                                         uint32_t a0, uint32_t a1, uint32_t a2, uint32_t a3,
                                         uint32_t b0, uint32_t b1)
{
    asm volatile("mma.sync.aligned.m16n8k8.row.col.f32.tf32.tf32.f32 "
                 "{%0,%1,%2,%3}, {%4,%5,%6,%7}, {%8,%9}, {%0,%1,%2,%3};"
                 : "+f"(d[0]), "+f"(d[1]), "+f"(d[2]), "+f"(d[3])
                 : "r"(a0), "r"(a1), "r"(a2), "r"(a3), "r"(b0), "r"(b1));
}

__device__ __forceinline__ float tf32_hi(float x)
{
    return __uint_as_float(__float_as_uint(x) & 0xFFFFE000u);
}

// ---------------------------------------------------------------------------
// Shared layout (float offsets)
// ---------------------------------------------------------------------------
#define CSTR 72
#define ASTR 20
#define BSTR 72
#define OFF_GF   0          // 64x64 fp32 exact (alpha-chain corrections)
#define OFF_GHI  4096       // 64x64 tf32-hi
#define OFF_GLO  8192       // 64x64 tf32-lo
#define OFF_C    12288      // 2 x 64 x CSTR fp32
#define OFF_ASEL 21504      // 2 batch x 2 split x 64 x ASTR
#define OFF_BSEL 26624      // 2 batch x 2 split x 16 x BSTR
#define OFF_INVD 31232      // 64
#define OFF_TOK  31296      // int [2 buf][2 batch][16]
#define OFF_XCH  31360      // 128
#define SMEM_FLOATS 31488   // 125952 bytes

// ---------------------------------------------------------------------------
// One chunk of T (<=16) steps for one batch-group (64 threads = 2 warps).
// ---------------------------------------------------------------------------
template<int T>
__device__ __forceinline__ void chunk(float* sm, int h, int w, int lane, int wg,
                                      int buf)
{
    const int*   tok  = (const int*)(sm + OFF_TOK) + buf * 32 + h * 16;
    const float* Gf   = sm + OFF_GF;
    const float* Ghi  = sm + OFF_GHI;
    const float* Glo  = sm + OFF_GLO;
    const float* invd = sm + OFF_INVD;
    float* Cb = sm + OFF_C    + h * 64 * CSTR;
    float* Ah = sm + OFF_ASEL + h * 2 * 64 * ASTR;   // [split][64][ASTR]
    float* Bh = sm + OFF_BSEL + h * 2 * 16 * BSTR;   // [split][16][BSTR]

    int s[16];
    #pragma unroll
    for (int j = 0; j < 16; j++) s[j] = tok[j];

    // beta bases from current C (broadcast-row LDS)
    float pend[16];
    #pragma unroll
    for (int j = 0; j < T; j++) pend[j] = Cb[s[j] * CSTR + w];

    // serial alpha chain with forward fan-out corrections (exact fp32)
    float alpha[16];
    #pragma unroll
    for (int u = 0; u < 16; u++) {
        if (u < T) {
            const float e = (w == s[u]) ? 1.f : 0.f;
            alpha[u] = fmaf(-invd[s[u]], pend[u], e);
            #pragma unroll
            for (int j = u + 1; j < T; j++)
                pend[j] = fmaf(Gf[s[u] * 64 + s[j]], alpha[u], pend[j]);
        } else {
            alpha[u] = 0.f;
        }
    }

    // stage B = alpha (hi/lo tf32 split): B[j][w]
    #pragma unroll
    for (int j = 0; j < 16; j++) {
        const float x  = alpha[j];
        const float hi = tf32_hi(x);
        Bh[j * BSTR + w]             = hi;
        Bh[16 * BSTR + j * BSTR + w] = tf32_hi(x - hi);
    }
    // stage A: A[x=w][j] = G[s_j][w] (hi/lo)
    #pragma unroll
    for (int j = 0; j < 16; j++) {
        Ah[w * ASTR + j]             = Ghi[s[j] * 64 + w];
        Ah[64 * ASTR + w * ASTR + j] = Glo[s[j] * 64 + w];
    }

    asm volatile("bar.sync %0, 64;" :: "r"(h + 1) : "memory");

    // ---- mma phase: warp wg owns columns [wg*32, wg*32+32) ----
    const int gid = lane >> 2, tig = lane & 3;
    float D[4][4][4];                       // [mi][nl][reg]

    #pragma unroll
    for (int mi = 0; mi < 4; mi++)
        #pragma unroll
        for (int nl = 0; nl < 4; nl++) {
            const int r0 = mi * 16 + gid;
            const int cb = (wg * 4 + nl) * 8 + tig * 2;
            const float2 t0 = *(const float2*)&Cb[r0 * CSTR + cb];
            const float2 t1 = *(const float2*)&Cb[(r0 + 8) * CSTR + cb];
            D[mi][nl][0] = t0.x; D[mi][nl][1] = t0.y;
            D[mi][nl][2] = t1.x; D[mi][nl][3] = t1.y;
        }

    #pragma unroll
    for (int kk = 0; kk < 2; kk++) {
        uint32_t Af[2][4][4];               // [split][mi][reg]
        #pragma unroll
        for (int mi = 0; mi < 4; mi++) {
            const int r0 = mi * 16 + gid;
            const int c0 = kk * 8 + tig;
            #pragma unroll
            for (int sp = 0; sp < 2; sp++) {
                const float* As = Ah + sp * 64 * ASTR;
                Af[sp][mi][0] = __float_as_uint(As[r0 * ASTR + c0]);
                Af[sp][mi][1] = __float_as_uint(As[(r0 + 8) * ASTR + c0]);
                Af[sp][mi][2] = __float_as_uint(As[r0 * ASTR + c0 + 4]);
                Af[sp][mi][3] = __float_as_uint(As[(r0 + 8) * ASTR + c0 + 4]);
            }
        }
        uint32_t Bf[2][4][2];               // [split][nl][reg]
        #pragma unroll
        for (int nl = 0; nl < 4; nl++) {
            const int kr = kk * 8 + tig;
            const int nc = (wg * 4 + nl) * 8 + gid;
            #pragma unroll
            for (int sp = 0; sp < 2; sp++) {
                const float* Bs = Bh + sp * 16 * BSTR;
                Bf[sp][nl][0] = __float_as_uint(Bs[kr * BSTR + nc]);
                Bf[sp][nl][1] = __float_as_uint(Bs[(kr + 4) * BSTR + nc]);
            }
        }
        // products hh, lh, hl (ll dropped)
        #pragma unroll
        for (int nl = 0; nl < 4; nl++)
            #pragma unroll
            for (int mi = 0; mi < 4; mi++) {
                mma_tf32(D[mi][nl], Af[0][mi][0], Af[0][mi][1], Af[0][mi][2],
                         Af[0][mi][3], Bf[0][nl][0], Bf[0][nl][1]);
                mma_tf32(D[mi][nl], Af[1][mi][0], Af[1][mi][1], Af[1][mi][2],
                         Af[1][mi][3], Bf[0][nl][0], Bf[0][nl][1]);
                mma_tf32(D[mi][nl], Af[0][mi][0], Af[0][mi][1], Af[0][mi][2],
                         Af[0][mi][3], Bf[1][nl][0], Bf[1][nl][1]);
            }
    }

    #pragma unroll
    for (int mi = 0; mi < 4; mi++)
        #pragma unroll
        for (int nl = 0; nl < 4; nl++) {
            const int r0 = mi * 16 + gid;
            const int cb = (wg * 4 + nl) * 8 + tig * 2;
            *(float2*)&Cb[r0 * CSTR + cb]       = make_float2(D[mi][nl][0], D[mi][nl][1]);
            *(float2*)&Cb[(r0 + 8) * CSTR + cb] = make_float2(D[mi][nl][2], D[mi][nl][3]);
        }

    asm volatile("bar.sync %0, 64;" :: "r"(h + 1) : "memory");
}

// ---------------------------------------------------------------------------
// Phase 2+3: coefficient scan with tensor-core chunk updates.
// grid 128 x block 128 (2 independent 64-thread batch-groups per block).
// ---------------------------------------------------------------------------
extern __shared__ float s_dyn[];

__global__ __launch_bounds__(128, 1)
void scan_kernel(const int* __restrict__ seq,
                 const float* __restrict__ read_w,
                 const float* __restrict__ read_b,
                 const float* __restrict__ out_w,
                 const float* __restrict__ out_b,
                 float* __restrict__ out)
{
    float* sm = s_dyn;
    const int tid  = threadIdx.x;
    const int lane = tid & 31;
    const int h    = tid >> 6;
    const int w    = tid & 63;
    const int wg   = (tid >> 5) & 1;
    const int b0   = blockIdx.x * 2;

    // ---- prologue ----
    for (int i = tid; i < V_ * V_; i += 128) {
        const float g  = g_G[i];
        const float hi = tf32_hi(g);
        sm[OFF_GF + i]  = g;
        sm[OFF_GHI + i] = hi;
        sm[OFF_GLO + i] = tf32_hi(g - hi);
    }
    for (int i = tid; i < 2 * 64 * CSTR; i += 128) sm[OFF_C + i] = 0.f;
    if (tid < V_) sm[OFF_INVD + tid] = g_invd[tid];

    int* tokb = (int*)(sm + OFF_TOK);
    if (tid < 16)                   tokb[tid]           = __ldg(seq + (long)b0 * L_ + tid);
    else if (tid >= 64 && tid < 80) tokb[16 + tid - 64] = __ldg(seq + (long)(b0 + 1) * L_ + (tid - 64));
    __syncthreads();

    // ---- 255 full chunks + tail (steps 4080..4094; slot 15 = query) ----
    #pragma unroll 1
    for (int c = 0; c < 255; c++) {
        const int nb = (c + 1) & 1;
        if (tid < 16)
            tokb[nb * 32 + tid] = __ldg(seq + (long)b0 * L_ + (c + 1) * 16 + tid);
        else if (tid >= 64 && tid < 80)
            tokb[nb * 32 + 16 + tid - 64] = __ldg(seq + (long)(b0 + 1) * L_ + (c + 1) * 16 + (tid - 64));

        chunk<16>(sm, h, w, lane, wg, c & 1);
    }
    chunk<15>(sm, h, w, lane, wg, 1);

    __syncthreads();

    // ---- epilogue ----
    float* Cb  = sm + OFF_C + h * 64 * CSTR;
    float* xch = sm + OFF_XCH;
    const int sq = ((const int*)(sm + OFF_TOK))[32 + h * 16 + 15];

    // coefficient vector of ctx in the k-basis: Aw[v] = C[sq][v]
    xch[tid] = Cb[sq * CSTR + w];
    __syncthreads();

    // ctx[i] = sum_v Aw[v] * K[v][i]
    float ctx = 0.f;
    #pragma unroll 8
    for (int v = 0; v < V_; v++)
        ctx = fmaf(xch[(h << 6) + v], __ldg(g_K + v * H_ + w), ctx);
    __syncthreads(); xch[tid] = ctx; __syncthreads();

    float r = read_b[w];
    #pragma unroll 8
    for (int j = 0; j < H_; j++) r = fmaf(xch[(h << 6) + j], read_w[j * H_ + w], r);
    __syncthreads(); xch[tid] = r; __syncthreads();

    float o = out_b[w];
    #pragma unroll 8
    for (int j = 0; j < H_; j++) o = fmaf(xch[(h << 6) + j], out_w[j * V_ + w], o);
    out[(b0 + h) * V_ + w] = o;
}

// ---------------------------------------------------------------------------
extern "C" void kernel_launch(void* const* d_in, const int* in_sizes, int n_in,
                              void* d_out, int out_size)
{
    const int*   seq     = (const int*)  d_in[0];
    const float* embed_W = (const float*)d_in[1];
    const float* ff_w1   = (const float*)d_in[2];
    const float* ff_b1   = (const float*)d_in[3];
    const float* ff_w2   = (const float*)d_in[4];
    const float* ff_b2   = (const float*)d_in[5];
    const float* ln_w    = (const float*)d_in[6];
    const float* ln_b    = (const float*)d_in[7];
    const float* read_w  = (const float*)d_in[8];
    const float* read_b  = (const float*)d_in[9];
    const float* out_w   = (const float*)d_in[10];
    const float* out_b   = (const float*)d_in[11];
    float* out = (float*)d_out;

    const int smem_bytes = SMEM_FLOATS * 4;
    cudaFuncSetAttribute(scan_kernel,
                         cudaFuncAttributeMaxDynamicSharedMemorySize, smem_bytes);

    build_table_kernel<<<V_, H_>>>(embed_W, ff_w1, ff_b1, ff_w2, ff_b2,
                                   ln_w, ln_b);
    build_gram_kernel<<<V_, H_>>>();
    scan_kernel<<<B_ / 2, 128, smem_bytes>>>(seq, read_w, read_b,
                                             out_w, out_b, out);
}

// round 8
// speedup vs baseline: 1.4094x; 1.4094x over previous
#include <cuda_runtime.h>
#include <cuda_bf16.h>
#include <cstdint>

#define B_ 256
#define L_ 4096
#define H_ 64
#define V_ 64

__device__ float g_K[V_ * H_];
__device__ float g_invd[V_];

// ---------------------------------------------------------------------------
// Phase 1: vocab table (V==64 collapses embed+FF+LN to a 64x64 LUT)
// ---------------------------------------------------------------------------
__global__ void build_table_kernel(const float* __restrict__ embed_W,
                                   const float* __restrict__ w1,
                                   const float* __restrict__ b1,
                                   const float* __restrict__ w2,
                                   const float* __restrict__ b2,
                                   const float* __restrict__ lnw,
                                   const float* __restrict__ lnb)
{
    __shared__ float e[H_], a[2 * H_], hrow[H_], red[H_];
    const int v = blockIdx.x, t = threadIdx.x;

    e[t] = embed_W[v * H_ + t];
    __syncthreads();

    float a0 = b1[t], a1 = b1[t + H_];
    #pragma unroll 8
    for (int k = 0; k < H_; k++) {
        float ek = e[k];
        a0 += ek * w1[k * 2 * H_ + t];
        a1 += ek * w1[k * 2 * H_ + t + H_];
    }
    a[t] = fmaxf(a0, 0.f); a[t + H_] = fmaxf(a1, 0.f);
    __syncthreads();

    float f = b2[t];
    #pragma unroll 8
    for (int o = 0; o < 2 * H_; o++) f += a[o] * w2[o * H_ + t];
    hrow[t] = e[t] + f;
    __syncthreads();

    float mu = 0.f;
    #pragma unroll 8
    for (int j = 0; j < H_; j++) mu += hrow[j];
    mu *= (1.f / H_);
    float var = 0.f;
    #pragma unroll 8
    for (int j = 0; j < H_; j++) { float d = hrow[j] - mu; var += d * d; }
    var *= (1.f / H_);

    float kv = (hrow[t] - mu) * rsqrtf(var + 1e-5f) * lnw[t] + lnb[t];
    g_K[v * H_ + t] = kv;
    red[t] = kv * kv;
    __syncthreads();
    if (t == 0) {
        float d = 0.f;
        #pragma unroll 8
        for (int j = 0; j < H_; j++) d += red[j];
        g_invd[v] = 1.f / (d + 1e-6f);
    }
}

// ---------------------------------------------------------------------------
// bf16 mma.sync m16n8k16 (valid on plain compute_103)
// ---------------------------------------------------------------------------
__device__ __forceinline__ void mma_bf16(float d[4], const uint32_t a[4],
                                         const uint32_t b[2])
{
    asm volatile("mma.sync.aligned.m16n8k16.row.col.f32.bf16.bf16.f32 "
                 "{%0,%1,%2,%3}, {%4,%5,%6,%7}, {%8,%9}, {%0,%1,%2,%3};"
                 : "+f"(d[0]), "+f"(d[1]), "+f"(d[2]), "+f"(d[3])
                 : "r"(a[0]), "r"(a[1]), "r"(a[2]), "r"(a[3]),
                   "r"(b[0]), "r"(b[1]));
}

// ---------------------------------------------------------------------------
// Shared layout (float offsets)
// ---------------------------------------------------------------------------
#define CSTR 72
#define PST  72
#define OFF_GF   0          // exact G 64x64 fp32
#define OFF_GP   4096       // packed u32: bf16 hi | lo<<16
#define OFF_CROW 8192       // 2 groups x 64 x CSTR (exported C rows)
#define OFF_AP   17408      // 2 groups x [2sp][8 pairs][PST] u32
#define OFF_BP   19712      // same
#define OFF_KSH  22016      // K table 64x64
#define OFF_INVD 26112
#define OFF_TOK  26176      // int [2 buf][2 group][16]
#define OFF_XCH  26240
#define SMEM_FLOATS 26368   // 105472 bytes

// ---------------------------------------------------------------------------
// One chunk of T (<=16) delta-rule steps for one 64-thread batch-group.
// C state lives in the register fragments D (accumulated by MMA); only the
// rows needed by the NEXT chunk's beta-gather are exported to shared.
// ---------------------------------------------------------------------------
template<int T, bool TAIL, bool FIRST>
__device__ __forceinline__ void chunk(float* sm, int h, int w, int lane, int wg,
                                      int buf, int nb, float (&D)[4][4][4])
{
    const int*      tok  = (const int*)(sm + OFF_TOK) + buf * 32 + h * 16;
    const float*    Gf   = sm + OFF_GF;
    const uint32_t* Gp   = (const uint32_t*)(sm + OFF_GP);
    const float*    invd = sm + OFF_INVD;
    float*    Crow = sm + OFF_CROW + h * 64 * CSTR;
    uint32_t* Ap   = (uint32_t*)(sm + OFF_AP) + h * 16 * PST;
    uint32_t* Bp   = (uint32_t*)(sm + OFF_BP) + h * 16 * PST;

    int s[16];
    #pragma unroll
    for (int j = 0; j < 16; j++) s[j] = tok[j];

    // beta bases (C at chunk start) from exported rows
    float pend[16];
    #pragma unroll
    for (int j = 0; j < 16; j++)
        pend[j] = (!FIRST && j < T) ? Crow[s[j] * CSTR + w] : 0.f;

    // exact serial alpha chain with forward fan-out corrections
    float alpha[16];
    #pragma unroll
    for (int u = 0; u < 16; u++) {
        if (u < T) {
            const float e = (w == s[u]) ? 1.f : 0.f;
            alpha[u] = fmaf(-invd[s[u]], pend[u], e);
            #pragma unroll
            for (int j = u + 1; j < 16; j++)
                if (j < T)
                    pend[j] = fmaf(Gf[s[u] * 64 + s[j]], alpha[u], pend[j]);
        } else alpha[u] = 0.f;
    }

    // stage B = alpha (hi/lo bf16 split), pair-major: Bp[sp*8+p][w]
    #pragma unroll
    for (int p = 0; p < 8; p++) {
        const float x0 = alpha[2 * p], x1 = alpha[2 * p + 1];
        const __nv_bfloat16 h0 = __float2bfloat16(x0), h1 = __float2bfloat16(x1);
        const float l0 = x0 - __bfloat162float(h0), l1 = x1 - __bfloat162float(h1);
        const __nv_bfloat16 c0 = __float2bfloat16(l0), c1 = __float2bfloat16(l1);
        Bp[p * PST + w]       = (uint32_t)__bfloat16_as_ushort(h0)
                              | ((uint32_t)__bfloat16_as_ushort(h1) << 16);
        Bp[(8 + p) * PST + w] = (uint32_t)__bfloat16_as_ushort(c0)
                              | ((uint32_t)__bfloat16_as_ushort(c1) << 16);
    }
    // stage A = Gsel^T from packed table: Ap[sp*8+p][x=w]
    #pragma unroll
    for (int p = 0; p < 8; p++) {
        const uint32_t q0 = Gp[s[2 * p] * 64 + w];
        const uint32_t q1 = Gp[s[2 * p + 1] * 64 + w];
        Ap[p * PST + w]       = (q0 & 0xFFFFu) | (q1 << 16);
        Ap[(8 + p) * PST + w] = (q0 >> 16) | (q1 & 0xFFFF0000u);
    }

    asm volatile("bar.sync %0, 64;" :: "r"(h + 1) : "memory");

    // rows needed by the next chunk
    uint64_t mask;
    if (TAIL) {
        mask = 1ull << s[15];
    } else {
        const int* ntok = (const int*)(sm + OFF_TOK) + nb * 32 + h * 16;
        mask = 0;
        #pragma unroll
        for (int j = 0; j < 16; j++) mask |= (1ull << ntok[j]);
    }

    const int gid = lane >> 2, tig = lane & 3;

    uint32_t Ahf[4][4], Alf[4][4];
    #pragma unroll
    for (int mi = 0; mi < 4; mi++) {
        const int r0 = mi * 16 + gid;
        Ahf[mi][0] = Ap[tig * PST + r0];          Ahf[mi][1] = Ap[tig * PST + r0 + 8];
        Ahf[mi][2] = Ap[(tig + 4) * PST + r0];    Ahf[mi][3] = Ap[(tig + 4) * PST + r0 + 8];
        Alf[mi][0] = Ap[(8 + tig) * PST + r0];    Alf[mi][1] = Ap[(8 + tig) * PST + r0 + 8];
        Alf[mi][2] = Ap[(12 + tig) * PST + r0];   Alf[mi][3] = Ap[(12 + tig) * PST + r0 + 8];
    }
    uint32_t Bhf[4][2], Blf[4][2];
    #pragma unroll
    for (int nl = 0; nl < 4; nl++) {
        const int nc = wg * 32 + nl * 8 + gid;
        Bhf[nl][0] = Bp[tig * PST + nc];       Bhf[nl][1] = Bp[(tig + 4) * PST + nc];
        Blf[nl][0] = Bp[(8 + tig) * PST + nc]; Blf[nl][1] = Bp[(12 + tig) * PST + nc];
    }

    #pragma unroll
    for (int mi = 0; mi < 4; mi++)
        #pragma unroll
        for (int nl = 0; nl < 4; nl++) {
            mma_bf16(D[mi][nl], Ahf[mi], Bhf[nl]);   // hh
            mma_bf16(D[mi][nl], Alf[mi], Bhf[nl]);   // lh
            mma_bf16(D[mi][nl], Ahf[mi], Blf[nl]);   // hl
        }

    // export owned rows hit by the mask
    #pragma unroll
    for (int mi = 0; mi < 4; mi++) {
        #pragma unroll
        for (int hr = 0; hr < 2; hr++) {
            const int r = mi * 16 + hr * 8 + gid;
            if ((mask >> r) & 1ull) {
                #pragma unroll
                for (int nl = 0; nl < 4; nl++) {
                    const int cb = wg * 32 + nl * 8 + tig * 2;
                    *(float2*)&Crow[r * CSTR + cb] =
                        make_float2(D[mi][nl][2 * hr], D[mi][nl][2 * hr + 1]);
                }
            }
        }
    }
    asm volatile("bar.sync %0, 64;" :: "r"(h + 1) : "memory");
}

// ---------------------------------------------------------------------------
// Phase 2+3: register-resident coefficient scan + readout.
// grid 128 x block 128 (2 independent 64-thread batch-groups).
// ---------------------------------------------------------------------------
extern __shared__ float s_dyn[];

__global__ __launch_bounds__(128, 1)
void scan_kernel(const int* __restrict__ seq,
                 const float* __restrict__ read_w,
                 const float* __restrict__ read_b,
                 const float* __restrict__ out_w,
                 const float* __restrict__ out_b,
                 float* __restrict__ out)
{
    float* sm = s_dyn;
    const int tid  = threadIdx.x;
    const int lane = tid & 31;
    const int h    = tid >> 6;
    const int w    = tid & 63;
    const int wg   = (tid >> 5) & 1;
    const int b0   = blockIdx.x * 2;

    // ---- prologue: K, invd, tokens, Gram (fused), packed G ----
    float4* Ksh4 = (float4*)(sm + OFF_KSH);
    for (int i = tid; i < V_ * H_ / 4; i += 128)
        Ksh4[i] = reinterpret_cast<const float4*>(g_K)[i];
    if (tid < V_) sm[OFF_INVD + tid] = g_invd[tid];
    int* tokb = (int*)(sm + OFF_TOK);
    if (tid < 16)                   tokb[tid]           = __ldg(seq + (long)b0 * L_ + tid);
    else if (tid >= 64 && tid < 80) tokb[16 + tid - 64] = __ldg(seq + (long)(b0 + 1) * L_ + (tid - 64));
    __syncthreads();

    {   // Gram: thread t computes row t>>1, 32 columns
        const int r = tid >> 1, ch = (tid & 1) * 32;
        float4 krow[16];
        #pragma unroll
        for (int i = 0; i < 16; i++) krow[i] = Ksh4[r * 16 + i];
        for (int c = ch; c < ch + 32; c++) {
            float a0 = 0.f, a1 = 0.f, a2 = 0.f, a3 = 0.f;
            #pragma unroll
            for (int i = 0; i < 16; i++) {
                const float4 kc = Ksh4[c * 16 + i];
                a0 = fmaf(krow[i].x, kc.x, a0);
                a1 = fmaf(krow[i].y, kc.y, a1);
                a2 = fmaf(krow[i].z, kc.z, a2);
                a3 = fmaf(krow[i].w, kc.w, a3);
            }
            sm[OFF_GF + r * 64 + c] = (a0 + a1) + (a2 + a3);
        }
    }
    __syncthreads();
    {   // packed bf16 hi|lo split of G
        uint32_t* Gp = (uint32_t*)(sm + OFF_GP);
        for (int i = tid; i < V_ * V_; i += 128) {
            const float g = sm[OFF_GF + i];
            const __nv_bfloat16 hi = __float2bfloat16(g);
            const __nv_bfloat16 lo = __float2bfloat16(g - __bfloat162float(hi));
            Gp[i] = (uint32_t)__bfloat16_as_ushort(hi)
                  | ((uint32_t)__bfloat16_as_ushort(lo) << 16);
        }
    }
    __syncthreads();

    float D[4][4][4];
    #pragma unroll
    for (int a = 0; a < 4; a++)
        #pragma unroll
        for (int b = 0; b < 4; b++)
            #pragma unroll
            for (int c = 0; c < 4; c++) D[a][b][c] = 0.f;

    // ---- chunk 0 ----
    if (tid < 16)                   tokb[32 + tid]           = __ldg(seq + (long)b0 * L_ + 16 + tid);
    else if (tid >= 64 && tid < 80) tokb[32 + 16 + tid - 64] = __ldg(seq + (long)(b0 + 1) * L_ + 16 + (tid - 64));
    chunk<16, false, true>(sm, h, w, lane, wg, 0, 1, D);

    // ---- chunks 1..254 ----
    #pragma unroll 1
    for (int c = 1; c < 255; c++) {
        const int nb = (c + 1) & 1;
        if (tid < 16)
            tokb[nb * 32 + tid] = __ldg(seq + (long)b0 * L_ + (c + 1) * 16 + tid);
        else if (tid >= 64 && tid < 80)
            tokb[nb * 32 + 16 + tid - 64] = __ldg(seq + (long)(b0 + 1) * L_ + (c + 1) * 16 + (tid - 64));
        chunk<16, false, false>(sm, h, w, lane, wg, c & 1, nb, D);
    }
    // ---- tail: steps 4080..4094, slot 15 = query ----
    chunk<15, true, false>(sm, h, w, lane, wg, 1, 0, D);

    __syncthreads();

    // ---- epilogue ----
    float* xch = sm + OFF_XCH;
    const int sq = ((const int*)(sm + OFF_TOK))[32 + h * 16 + 15];
    xch[tid] = (sm + OFF_CROW + h * 64 * CSTR)[sq * CSTR + w];
    __syncthreads();

    float ctx = 0.f;
    #pragma unroll 8
    for (int v = 0; v < V_; v++)
        ctx = fmaf(xch[(h << 6) + v], sm[OFF_KSH + v * 64 + w], ctx);
    __syncthreads(); xch[tid] = ctx; __syncthreads();

    float r = read_b[w];
    #pragma unroll 8
    for (int j = 0; j < H_; j++) r = fmaf(xch[(h << 6) + j], read_w[j * H_ + w], r);
    __syncthreads(); xch[tid] = r; __syncthreads();

    float o = out_b[w];
    #pragma unroll 8
    for (int j = 0; j < H_; j++) o = fmaf(xch[(h << 6) + j], out_w[j * V_ + w], o);
    out[(b0 + h) * V_ + w] = o;
}

// ---------------------------------------------------------------------------
extern "C" void kernel_launch(void* const* d_in, const int* in_sizes, int n_in,
                              void* d_out, int out_size)
{
    const int*   seq     = (const int*)  d_in[0];
    const float* embed_W = (const float*)d_in[1];
    const float* ff_w1   = (const float*)d_in[2];
    const float* ff_b1   = (const float*)d_in[3];
    const float* ff_w2   = (const float*)d_in[4];
    const float* ff_b2   = (const float*)d_in[5];
    const float* ln_w    = (const float*)d_in[6];
    const float* ln_b    = (const float*)d_in[7];
    const float* read_w  = (const float*)d_in[8];
    const float* read_b  = (const float*)d_in[9];
    const float* out_w   = (const float*)d_in[10];
    const float* out_b   = (const float*)d_in[11];
    float* out = (float*)d_out;

    const int smem_bytes = SMEM_FLOATS * 4;
    cudaFuncSetAttribute(scan_kernel,
                         cudaFuncAttributeMaxDynamicSharedMemorySize, smem_bytes);

    build_table_kernel<<<V_, H_>>>(embed_W, ff_w1, ff_b1, ff_w2, ff_b2,
                                   ln_w, ln_b);
    scan_kernel<<<B_ / 2, 128, smem_bytes>>>(seq, read_w, read_b,
                                             out_w, out_b, out);
}